// round 11
// baseline (speedup 1.0000x reference)
#include <cuda_runtime.h>
#include <math.h>

#define N_NODES 100000
#define N_EDGES 3200000
#define NBLK ((N_NODES + 255) / 256)   // 391 scan blocks

// ---------------- scratch (static device globals; no allocation) ----------------
__device__ int    g_is64;
__device__ float  g_deg [N_NODES];
__device__ float  g_dinv[N_NODES];
__device__ int    g_cnt [N_NODES];
__device__ int    g_rowstart[N_NODES];
__device__ int    g_bsum[NBLK];
__device__ int    g_src [N_EDGES];
__device__ int    g_dst [N_EDGES];
__device__ int    g_esrc [N_EDGES];   // CSC: source per slot
__device__ float  g_enorm[N_EDGES];   // CSC: norm per slot
__device__ float  g_h1  [N_NODES * 16];
__device__ float2 g_h2  [N_NODES];
__device__ float2 g_agg2i[N_NODES];

// ---------------- kernels ----------------

// Detect whether edge_index buffer is int64 (odd 32-bit words all zero) or int32.
__global__ void k_detect(const unsigned int* __restrict__ ei_raw) {
    if (threadIdx.x == 0 && blockIdx.x == 0) {
        int is64 = 1;
        for (int i = 0; i < 1024; i++) {
            if (ei_raw[2 * i + 1] != 0u) { is64 = 0; break; }
        }
        g_is64 = is64;
    }
}

// deg[i] = 1 (self-loop weight), cnt[i] = 0
__global__ void k_zero() {
    int i = blockIdx.x * blockDim.x + threadIdx.x;
    if (i < N_NODES) { g_deg[i] = 1.0f; g_cnt[i] = 0; }
}

// decode idx (int32 or int64) -> int32; weighted degree + count histogram at dst
__global__ void k_deg(const unsigned int* __restrict__ ei_raw, const float* __restrict__ w) {
    int e = blockIdx.x * blockDim.x + threadIdx.x;
    if (e >= N_EDGES) return;
    int s, d;
    if (g_is64) {
        s = (int)ei_raw[2 * (size_t)e];
        d = (int)ei_raw[2 * ((size_t)N_EDGES + e)];
    } else {
        s = (int)ei_raw[e];
        d = (int)ei_raw[N_EDGES + e];
    }
    s = min(max(s, 0), N_NODES - 1);
    d = min(max(d, 0), N_NODES - 1);
    g_src[e] = s;
    g_dst[e] = d;
    atomicAdd(&g_deg[d], w[e]);
    atomicAdd(&g_cnt[d], 1);
}

// per-block sums of cnt
__global__ void k_bsum() {
    __shared__ int s[256];
    int i = blockIdx.x * 256 + threadIdx.x;
    s[threadIdx.x] = (i < N_NODES) ? g_cnt[i] : 0;
    __syncthreads();
    for (int o = 128; o; o >>= 1) {
        if (threadIdx.x < o) s[threadIdx.x] += s[threadIdx.x + o];
        __syncthreads();
    }
    if (threadIdx.x == 0) g_bsum[blockIdx.x] = s[0];
}

// exclusive scan of NBLK block sums (single block, Hillis-Steele over 512)
__global__ void k_bscan() {
    __shared__ int s[512];
    int t = threadIdx.x;
    int v = (t < NBLK) ? g_bsum[t] : 0;
    s[t] = v;
    __syncthreads();
    for (int o = 1; o < 512; o <<= 1) {
        int add = (t >= o) ? s[t - o] : 0;
        __syncthreads();
        s[t] += add;
        __syncthreads();
    }
    if (t < NBLK) g_bsum[t] = s[t] - v;   // exclusive
}

// per-block exclusive scan + block offset -> rowstart; dinv; reset cnt
__global__ void k_scan3() {
    __shared__ int s[256];
    int t = threadIdx.x;
    int i = blockIdx.x * 256 + t;
    int v = (i < N_NODES) ? g_cnt[i] : 0;
    s[t] = v;
    __syncthreads();
    for (int o = 1; o < 256; o <<= 1) {
        int add = (t >= o) ? s[t - o] : 0;
        __syncthreads();
        s[t] += add;
        __syncthreads();
    }
    if (i < N_NODES) {
        g_rowstart[i] = g_bsum[blockIdx.x] + s[t] - v;  // exclusive prefix
        g_dinv[i] = rsqrtf(g_deg[i]);                   // deg >= 1 always
        g_cnt[i] = 0;
    }
}

// place edges into CSC slots; precompute norm
__global__ void k_place(const float* __restrict__ w) {
    int e = blockIdx.x * blockDim.x + threadIdx.x;
    if (e >= N_EDGES) return;
    int s = g_src[e];
    int d = g_dst[e];
    float nm = g_dinv[s] * w[e] * g_dinv[d];
    int pos = g_rowstart[d] + atomicAdd(&g_cnt[d], 1);
    g_esrc[pos] = s;
    g_enorm[pos] = nm;
}

// h1 = x @ W1
__global__ void k_h1(const float* __restrict__ x, const float* __restrict__ W1) {
    __shared__ float sW[64 * 16];
    for (int t = threadIdx.x; t < 64 * 16; t += blockDim.x) sW[t] = W1[t];
    __syncthreads();

    int i = blockIdx.x * blockDim.x + threadIdx.x;
    if (i >= N_NODES) return;

    float acc[16];
#pragma unroll
    for (int j = 0; j < 16; j++) acc[j] = 0.0f;

    const float4* xr = (const float4*)(x + (size_t)i * 64);
#pragma unroll
    for (int k4 = 0; k4 < 16; k4++) {
        float4 v = __ldg(xr + k4);
        int k = k4 * 4;
#pragma unroll
        for (int j = 0; j < 16; j++) {
            acc[j] = fmaf(v.x, sW[(k + 0) * 16 + j],
                     fmaf(v.y, sW[(k + 1) * 16 + j],
                     fmaf(v.z, sW[(k + 2) * 16 + j],
                     fmaf(v.w, sW[(k + 3) * 16 + j], acc[j]))));
        }
    }
#pragma unroll
    for (int j = 0; j < 16; j++) g_h1[(size_t)i * 16 + j] = acc[j];
}

// warp per node: agg1 = b1 + dinv^2*h1[i] + sum norm*h1[src]; relu; @W2 -> h2, agg2 init
// lanes 0-15 handle even edges (feature = lane), lanes 16-31 odd edges.
__global__ void k_gather1(const float* __restrict__ b1, const float* __restrict__ W2,
                          const float* __restrict__ b2) {
    int wid = (blockIdx.x * blockDim.x + threadIdx.x) >> 5;
    if (wid >= N_NODES) return;
    int lane = threadIdx.x & 31;
    int half = lane >> 4;
    int f = lane & 15;
    int start = g_rowstart[wid];
    int len = g_cnt[wid];

    float acc = 0.0f;
    for (int e = half; e < len; e += 2) {
        int src = g_esrc[start + e];          // broadcast within half-warp
        float nm = g_enorm[start + e];
        acc = fmaf(nm, g_h1[(size_t)src * 16 + f], acc);
    }
    acc += __shfl_xor_sync(0xffffffffu, acc, 16);   // combine halves

    float dinv = g_dinv[wid];
    float d2 = dinv * dinv;
    float a = __ldg(b1 + f) + d2 * g_h1[(size_t)wid * 16 + f] + acc;
    a = fmaxf(a, 0.0f);                              // relu

    float c0 = a * __ldg(W2 + f * 2 + 0);
    float c1 = a * __ldg(W2 + f * 2 + 1);
#pragma unroll
    for (int o = 8; o; o >>= 1) {                    // reduce over 16 features
        c0 += __shfl_xor_sync(0xffffffffu, c0, o);
        c1 += __shfl_xor_sync(0xffffffffu, c1, o);
    }
    if (lane == 0) {
        g_h2[wid] = make_float2(c0, c1);
        g_agg2i[wid] = make_float2(__ldg(b2 + 0) + c0 * d2,
                                   __ldg(b2 + 1) + c1 * d2);
    }
}

// warp per node: x2 = agg2i + sum norm*h2[src]; fused head; write outputs
__global__ void k_gather2(const float* __restrict__ lin_w, const float* __restrict__ lin_b,
                          float* __restrict__ out) {
    int wid = (blockIdx.x * blockDim.x + threadIdx.x) >> 5;
    if (wid >= N_NODES) return;
    int lane = threadIdx.x & 31;
    int start = g_rowstart[wid];
    int len = g_cnt[wid];

    float a0 = 0.0f, a1 = 0.0f;
    for (int e = lane; e < len; e += 32) {
        int src = g_esrc[start + e];
        float nm = g_enorm[start + e];
        float2 h = g_h2[src];
        a0 = fmaf(nm, h.x, a0);
        a1 = fmaf(nm, h.y, a1);
    }
#pragma unroll
    for (int o = 16; o; o >>= 1) {
        a0 += __shfl_xor_sync(0xffffffffu, a0, o);
        a1 += __shfl_xor_sync(0xffffffffu, a1, o);
    }
    if (lane == 0) {
        float2 init = g_agg2i[wid];
        float x0 = init.x + a0;
        float x1 = init.y + a1;
        float r0 = fmaxf(x0, 0.0f);
        float r1 = fmaxf(x1, 0.0f);
        float z = fmaf(r0, __ldg(lin_w + 0), fmaf(r1, __ldg(lin_w + 1), __ldg(lin_b)));
        out[wid] = 1.0f / (1.0f + expf(-z));
        out[N_NODES + 2 * wid + 0] = x0;
        out[N_NODES + 2 * wid + 1] = x1;
    }
}

// ---------------- launch ----------------
extern "C" void kernel_launch(void* const* d_in, const int* in_sizes, int n_in,
                              void* d_out, int out_size) {
    const float*        x     = (const float*)d_in[0];
    const unsigned int* ei    = (const unsigned int*)d_in[1];
    const float*        ew    = (const float*)d_in[2];
    const float*        W1    = (const float*)d_in[3];
    const float*        b1    = (const float*)d_in[4];
    const float*        W2    = (const float*)d_in[5];
    const float*        b2    = (const float*)d_in[6];
    const float*        lin_w = (const float*)d_in[7];
    const float*        lin_b = (const float*)d_in[8];
    float* out = (float*)d_out;

    const int TB = 256;
    const int GN = (N_NODES + TB - 1) / TB;
    const int GE = (N_EDGES + TB - 1) / TB;
    const int GW = (N_NODES + 7) / 8;      // warp-per-node kernels, 8 warps/block

    k_detect <<<1, 32>>>(ei);
    k_zero   <<<GN, TB>>>();
    k_deg    <<<GE, TB>>>(ei, ew);
    k_bsum   <<<NBLK, 256>>>();
    k_bscan  <<<1, 512>>>();
    k_scan3  <<<NBLK, 256>>>();
    k_place  <<<GE, TB>>>(ew);
    k_h1     <<<GN, TB>>>(x, W1);
    k_gather1<<<GW, TB>>>(b1, W2, b2);
    k_gather2<<<GW, TB>>>(lin_w, lin_b, out);
}

// round 12
// speedup vs baseline: 1.1096x; 1.1096x over previous
#include <cuda_runtime.h>
#include <math.h>

#define N_NODES 100000
#define N_EDGES 3200000
#define NBLK ((N_NODES + 255) / 256)   // 391 scan blocks

// ---------------- scratch (static device globals; no allocation) ----------------
__device__ int    g_is64;
__device__ float  g_dinv[N_NODES];
__device__ int    g_cnt [N_NODES];
__device__ int    g_rowstart[N_NODES];
__device__ int    g_bsum[NBLK];
__device__ int2   g_edge[N_EDGES];    // CSC slot: {src, float_bits(w)}
__device__ float  g_h1  [N_NODES * 16];
__device__ float2 g_h2  [N_NODES];
__device__ float2 g_agg2i[N_NODES];

// ---------------- kernels ----------------

// zero cnt; block 0 warp 0 detects int64 vs int32 edge_index encoding
__global__ void k_init(const unsigned int* __restrict__ ei_raw) {
    int i = blockIdx.x * blockDim.x + threadIdx.x;
    if (i < N_NODES) g_cnt[i] = 0;
    if (blockIdx.x == 0 && threadIdx.x < 32) {
        unsigned int any = 0;
        for (int j = threadIdx.x; j < 1024; j += 32) any |= ei_raw[2 * j + 1];
        any = __ballot_sync(0xffffffffu, any != 0u);
        if (threadIdx.x == 0) g_is64 = (any == 0u) ? 1 : 0;
    }
}

// count histogram at dst (dst-only decode, int atomic only)
__global__ void k_cnt(const unsigned int* __restrict__ ei_raw) {
    int e = blockIdx.x * blockDim.x + threadIdx.x;
    if (e >= N_EDGES) return;
    int d = g_is64 ? (int)ei_raw[2 * ((size_t)N_EDGES + e)]
                   : (int)ei_raw[(size_t)N_EDGES + e];
    d = min(max(d, 0), N_NODES - 1);
    atomicAdd(&g_cnt[d], 1);
}

// per-block sums of cnt (shuffle reduce)
__global__ void k_bsum() {
    __shared__ int sm[8];
    int i = blockIdx.x * 256 + threadIdx.x;
    int v = (i < N_NODES) ? g_cnt[i] : 0;
#pragma unroll
    for (int o = 16; o; o >>= 1) v += __shfl_xor_sync(0xffffffffu, v, o);
    if ((threadIdx.x & 31) == 0) sm[threadIdx.x >> 5] = v;
    __syncthreads();
    if (threadIdx.x == 0) {
        int t = 0;
#pragma unroll
        for (int j = 0; j < 8; j++) t += sm[j];
        g_bsum[blockIdx.x] = t;
    }
}

// per-block exclusive scan + inline prefix of block sums -> rowstart; reset cnt
__global__ void k_scan() {
    __shared__ int s[256];
    __shared__ int boff;
    int t = threadIdx.x;
    int i = blockIdx.x * 256 + t;
    int v = (i < N_NODES) ? g_cnt[i] : 0;
    s[t] = v;
    __syncthreads();
    for (int o = 1; o < 256; o <<= 1) {
        int add = (t >= o) ? s[t - o] : 0;
        __syncthreads();
        s[t] += add;
        __syncthreads();
    }
    if (t < 32) {
        int acc = 0;
        for (int j = t; j < blockIdx.x; j += 32) acc += g_bsum[j];
#pragma unroll
        for (int o = 16; o; o >>= 1) acc += __shfl_xor_sync(0xffffffffu, acc, o);
        if (t == 0) boff = acc;
    }
    __syncthreads();
    if (i < N_NODES) {
        g_rowstart[i] = boff + s[t] - v;   // exclusive prefix
        g_cnt[i] = 0;
    }
}

// place edges into CSC slots: one packed int2 {src, w} per slot
__global__ void k_place(const unsigned int* __restrict__ ei_raw, const float* __restrict__ w) {
    int e = blockIdx.x * blockDim.x + threadIdx.x;
    if (e >= N_EDGES) return;
    int s, d;
    if (g_is64) {
        s = (int)ei_raw[2 * (size_t)e];
        d = (int)ei_raw[2 * ((size_t)N_EDGES + e)];
    } else {
        s = (int)ei_raw[e];
        d = (int)ei_raw[(size_t)N_EDGES + e];
    }
    s = min(max(s, 0), N_NODES - 1);
    d = min(max(d, 0), N_NODES - 1);
    int pos = g_rowstart[d] + atomicAdd(&g_cnt[d], 1);
    g_edge[pos] = make_int2(s, __float_as_int(w[e]));
}

// warp per node: deg = 1 + sum(w); dinv = rsqrt(deg)   (atomic-free)
__global__ void k_degw() {
    int wid = (blockIdx.x * blockDim.x + threadIdx.x) >> 5;
    if (wid >= N_NODES) return;
    int lane = threadIdx.x & 31;
    int start = g_rowstart[wid];
    int len = g_cnt[wid];
    float sum = 0.0f;
    for (int e = lane; e < len; e += 32)
        sum += __int_as_float(g_edge[start + e].y);
#pragma unroll
    for (int o = 16; o; o >>= 1) sum += __shfl_xor_sync(0xffffffffu, sum, o);
    if (lane == 0) g_dinv[wid] = rsqrtf(1.0f + sum);
}

// h1 = x @ W1
__global__ void k_h1(const float* __restrict__ x, const float* __restrict__ W1) {
    __shared__ float sW[64 * 16];
    for (int t = threadIdx.x; t < 64 * 16; t += blockDim.x) sW[t] = W1[t];
    __syncthreads();

    int i = blockIdx.x * blockDim.x + threadIdx.x;
    if (i >= N_NODES) return;

    float acc[16];
#pragma unroll
    for (int j = 0; j < 16; j++) acc[j] = 0.0f;

    const float4* xr = (const float4*)(x + (size_t)i * 64);
#pragma unroll
    for (int k4 = 0; k4 < 16; k4++) {
        float4 v = __ldg(xr + k4);
        int k = k4 * 4;
#pragma unroll
        for (int j = 0; j < 16; j++) {
            acc[j] = fmaf(v.x, sW[(k + 0) * 16 + j],
                     fmaf(v.y, sW[(k + 1) * 16 + j],
                     fmaf(v.z, sW[(k + 2) * 16 + j],
                     fmaf(v.w, sW[(k + 3) * 16 + j], acc[j]))));
        }
    }
#pragma unroll
    for (int j = 0; j < 16; j++) g_h1[(size_t)i * 16 + j] = acc[j];
}

// warp per node: agg1 = b1 + dinv^2*h1[i] + sum norm*h1[src]; relu; @W2 -> h2, agg2 init
// lanes 0-15 handle even edges (feature = lane&15), lanes 16-31 odd edges; norm on the fly.
__global__ void k_gather1(const float* __restrict__ b1, const float* __restrict__ W2,
                          const float* __restrict__ b2) {
    int wid = (blockIdx.x * blockDim.x + threadIdx.x) >> 5;
    if (wid >= N_NODES) return;
    int lane = threadIdx.x & 31;
    int half = lane >> 4;
    int f = lane & 15;
    int start = g_rowstart[wid];
    int len = g_cnt[wid];
    float dinvD = g_dinv[wid];

    float acc = 0.0f;
    for (int e = half; e < len; e += 2) {
        int2 ed = g_edge[start + e];                 // broadcast in half-warp
        float nm = g_dinv[ed.x] * __int_as_float(ed.y) * dinvD;
        acc = fmaf(nm, g_h1[(size_t)ed.x * 16 + f], acc);
    }
    acc += __shfl_xor_sync(0xffffffffu, acc, 16);    // combine halves

    float d2 = dinvD * dinvD;
    float a = __ldg(b1 + f) + d2 * g_h1[(size_t)wid * 16 + f] + acc;
    a = fmaxf(a, 0.0f);                              // relu

    float c0 = a * __ldg(W2 + f * 2 + 0);
    float c1 = a * __ldg(W2 + f * 2 + 1);
#pragma unroll
    for (int o = 8; o; o >>= 1) {                    // reduce over 16 features
        c0 += __shfl_xor_sync(0xffffffffu, c0, o);
        c1 += __shfl_xor_sync(0xffffffffu, c1, o);
    }
    if (lane == 0) {
        g_h2[wid] = make_float2(c0, c1);
        g_agg2i[wid] = make_float2(__ldg(b2 + 0) + c0 * d2,
                                   __ldg(b2 + 1) + c1 * d2);
    }
}

// warp per node: x2 = agg2i + sum norm*h2[src]; fused head; write outputs
__global__ void k_gather2(const float* __restrict__ lin_w, const float* __restrict__ lin_b,
                          float* __restrict__ out) {
    int wid = (blockIdx.x * blockDim.x + threadIdx.x) >> 5;
    if (wid >= N_NODES) return;
    int lane = threadIdx.x & 31;
    int start = g_rowstart[wid];
    int len = g_cnt[wid];
    float dinvD = g_dinv[wid];

    float a0 = 0.0f, a1 = 0.0f;
    for (int e = lane; e < len; e += 32) {
        int2 ed = g_edge[start + e];
        float nm = g_dinv[ed.x] * __int_as_float(ed.y) * dinvD;
        float2 h = g_h2[ed.x];
        a0 = fmaf(nm, h.x, a0);
        a1 = fmaf(nm, h.y, a1);
    }
#pragma unroll
    for (int o = 16; o; o >>= 1) {
        a0 += __shfl_xor_sync(0xffffffffu, a0, o);
        a1 += __shfl_xor_sync(0xffffffffu, a1, o);
    }
    if (lane == 0) {
        float2 init = g_agg2i[wid];
        float x0 = init.x + a0;
        float x1 = init.y + a1;
        float r0 = fmaxf(x0, 0.0f);
        float r1 = fmaxf(x1, 0.0f);
        float z = fmaf(r0, __ldg(lin_w + 0), fmaf(r1, __ldg(lin_w + 1), __ldg(lin_b)));
        out[wid] = 1.0f / (1.0f + expf(-z));
        out[N_NODES + 2 * wid + 0] = x0;
        out[N_NODES + 2 * wid + 1] = x1;
    }
}

// ---------------- launch ----------------
extern "C" void kernel_launch(void* const* d_in, const int* in_sizes, int n_in,
                              void* d_out, int out_size) {
    const float*        x     = (const float*)d_in[0];
    const unsigned int* ei    = (const unsigned int*)d_in[1];
    const float*        ew    = (const float*)d_in[2];
    const float*        W1    = (const float*)d_in[3];
    const float*        b1    = (const float*)d_in[4];
    const float*        W2    = (const float*)d_in[5];
    const float*        b2    = (const float*)d_in[6];
    const float*        lin_w = (const float*)d_in[7];
    const float*        lin_b = (const float*)d_in[8];
    float* out = (float*)d_out;

    const int TB = 256;
    const int GN = (N_NODES + TB - 1) / TB;
    const int GE = (N_EDGES + TB - 1) / TB;
    const int GW = (N_NODES + 7) / 8;      // warp-per-node kernels, 8 warps/block

    k_init   <<<GN, TB>>>(ei);
    k_cnt    <<<GE, TB>>>(ei);
    k_bsum   <<<NBLK, 256>>>();
    k_scan   <<<NBLK, 256>>>();
    k_place  <<<GE, TB>>>(ei, ew);
    k_degw   <<<GW, TB>>>();
    k_h1     <<<GN, TB>>>(x, W1);
    k_gather1<<<GW, TB>>>(b1, W2, b2);
    k_gather2<<<GW, TB>>>(lin_w, lin_b, out);
}